// round 2
// baseline (speedup 1.0000x reference)
#include <cuda_runtime.h>
#include <cuda_bf16.h>
#include <stdint.h>

// RBF logits: out[b,c] = 2 * dot(x[b], w[c]) - ||x[b]||^2 - ||w[c]||^2
// B=32768, C=4096, D=64 (fp32 in, fp32 out). Write-bound: 512MB output.
// Strategy: 128x128 tile / CTA, bf16 mma.sync.m16n8k16, fp32 accum.
// x_sq / w_sq computed from fp32 globals for accuracy.

#define BM 128
#define BN 128
#define KD 64
#define PAD 72  // smem row stride in bf16 elems (144B): conflict-free frag loads

static __device__ __forceinline__ uint32_t pack_bf16(float a, float b) {
    __nv_bfloat162 h = __floats2bfloat162_rn(a, b);
    return *reinterpret_cast<uint32_t*>(&h);
}

__global__ __launch_bounds__(256)
void rbf_logits_kernel(const float* __restrict__ x,
                       const float* __restrict__ w,
                       float* __restrict__ out,
                       int B, int C) {
    __shared__ __nv_bfloat16 Xs[BM * PAD];
    __shared__ __nv_bfloat16 Ws[BN * PAD];
    __shared__ float xsq_s[BM];
    __shared__ float wsq_s[BN];

    const int tid  = threadIdx.x;
    const int row0 = blockIdx.y * BM;   // batch block
    const int col0 = blockIdx.x * BN;   // class block

    // ---- Load X tile (128x64 fp32 -> bf16), fully coalesced float4 reads ----
    {
        const float4* xg = reinterpret_cast<const float4*>(x + (size_t)row0 * KD);
        #pragma unroll
        for (int i = tid; i < BM * KD / 4; i += 256) {
            int r  = i >> 4;        // 16 float4 per row
            int c4 = i & 15;
            float4 v = xg[(size_t)r * 16 + c4];
            uint32_t* dst = reinterpret_cast<uint32_t*>(&Xs[r * PAD + c4 * 4]);
            dst[0] = pack_bf16(v.x, v.y);
            dst[1] = pack_bf16(v.z, v.w);
        }
    }
    // ---- Load W tile (128x64 fp32 -> bf16) ----
    {
        const float4* wg = reinterpret_cast<const float4*>(w + (size_t)col0 * KD);
        #pragma unroll
        for (int i = tid; i < BN * KD / 4; i += 256) {
            int r  = i >> 4;
            int c4 = i & 15;
            float4 v = wg[(size_t)r * 16 + c4];
            uint32_t* dst = reinterpret_cast<uint32_t*>(&Ws[r * PAD + c4 * 4]);
            dst[0] = pack_bf16(v.x, v.y);
            dst[1] = pack_bf16(v.z, v.w);
        }
    }

    // ---- Row sum-of-squares from fp32 globals (L2 hits; cheap) ----
    if (tid < BM) {
        const float4* p = reinterpret_cast<const float4*>(x + (size_t)(row0 + tid) * KD);
        float s = 0.f;
        #pragma unroll
        for (int j = 0; j < 16; j++) {
            float4 v = p[j];
            s += v.x * v.x + v.y * v.y + v.z * v.z + v.w * v.w;
        }
        xsq_s[tid] = s;
    } else {
        int r = tid - BM;
        const float4* p = reinterpret_cast<const float4*>(w + (size_t)(col0 + r) * KD);
        float s = 0.f;
        #pragma unroll
        for (int j = 0; j < 16; j++) {
            float4 v = p[j];
            s += v.x * v.x + v.y * v.y + v.z * v.z + v.w * v.w;
        }
        wsq_s[r] = s;
    }

    __syncthreads();

    // ---- Warp tiling: 8 warps as 2(M) x 4(N); each warp 64x32 ----
    const int wid    = tid >> 5;
    const int lane   = tid & 31;
    const int warp_m = wid >> 2;          // 0..1
    const int warp_n = wid & 3;           // 0..3
    const int m_base = warp_m * 64;
    const int n_base = warp_n * 32;
    const int lr = lane >> 2;             // 0..7
    const int lq = lane & 3;              // 0..3

    float acc[4][4][4];
    #pragma unroll
    for (int mi = 0; mi < 4; mi++)
        #pragma unroll
        for (int ni = 0; ni < 4; ni++)
            #pragma unroll
            for (int e = 0; e < 4; e++)
                acc[mi][ni][e] = 0.f;

    #pragma unroll
    for (int k0 = 0; k0 < KD; k0 += 16) {
        // A fragments: m16n8k16 row-major
        uint32_t afrag[4][4];
        #pragma unroll
        for (int mi = 0; mi < 4; mi++) {
            int r = m_base + mi * 16 + lr;
            const __nv_bfloat16* base = &Xs[r * PAD + k0 + lq * 2];
            afrag[mi][0] = *reinterpret_cast<const uint32_t*>(base);
            afrag[mi][1] = *reinterpret_cast<const uint32_t*>(base + 8 * PAD);
            afrag[mi][2] = *reinterpret_cast<const uint32_t*>(base + 8);
            afrag[mi][3] = *reinterpret_cast<const uint32_t*>(base + 8 * PAD + 8);
        }
        // B fragments: col-major (Ws is [n][k], n-major = B col-major)
        uint32_t bfrag[4][2];
        #pragma unroll
        for (int ni = 0; ni < 4; ni++) {
            int n = n_base + ni * 8 + lr;
            const __nv_bfloat16* base = &Ws[n * PAD + k0 + lq * 2];
            bfrag[ni][0] = *reinterpret_cast<const uint32_t*>(base);
            bfrag[ni][1] = *reinterpret_cast<const uint32_t*>(base + 8);
        }
        #pragma unroll
        for (int mi = 0; mi < 4; mi++) {
            #pragma unroll
            for (int ni = 0; ni < 4; ni++) {
                asm volatile(
                    "mma.sync.aligned.m16n8k16.row.col.f32.bf16.bf16.f32 "
                    "{%0,%1,%2,%3}, {%4,%5,%6,%7}, {%8,%9}, {%0,%1,%2,%3};\n"
                    : "+f"(acc[mi][ni][0]), "+f"(acc[mi][ni][1]),
                      "+f"(acc[mi][ni][2]), "+f"(acc[mi][ni][3])
                    : "r"(afrag[mi][0]), "r"(afrag[mi][1]),
                      "r"(afrag[mi][2]), "r"(afrag[mi][3]),
                      "r"(bfrag[ni][0]), "r"(bfrag[ni][1]));
            }
        }
    }

    // ---- Epilogue: out = 2*acc - xsq[row] - wsq[col], float2 stores ----
    #pragma unroll
    for (int mi = 0; mi < 4; mi++) {
        int rl0 = m_base + mi * 16 + lr;      // rows rl0, rl0+8
        float xs0 = xsq_s[rl0];
        float xs1 = xsq_s[rl0 + 8];
        #pragma unroll
        for (int ni = 0; ni < 4; ni++) {
            int cl = n_base + ni * 8 + lq * 2;
            float ws0 = wsq_s[cl];
            float ws1 = wsq_s[cl + 1];
            size_t g0 = (size_t)(row0 + rl0) * C + (col0 + cl);
            size_t g1 = (size_t)(row0 + rl0 + 8) * C + (col0 + cl);
            float2 v0 = make_float2(2.f * acc[mi][ni][0] - xs0 - ws0,
                                    2.f * acc[mi][ni][1] - xs0 - ws1);
            float2 v1 = make_float2(2.f * acc[mi][ni][2] - xs1 - ws0,
                                    2.f * acc[mi][ni][3] - xs1 - ws1);
            *reinterpret_cast<float2*>(out + g0) = v0;
            *reinterpret_cast<float2*>(out + g1) = v1;
        }
    }
}

extern "C" void kernel_launch(void* const* d_in, const int* in_sizes, int n_in,
                              void* d_out, int out_size) {
    const float* x = (const float*)d_in[0];
    const float* w = (const float*)d_in[1];
    float* out = (float*)d_out;
    int B = in_sizes[0] / KD;   // 32768
    int C = in_sizes[1] / KD;   // 4096

    dim3 grid(C / BN, B / BM);  // (32, 256)
    dim3 block(256);
    rbf_logits_kernel<<<grid, block>>>(x, w, out, B, C);
}

// round 4
// speedup vs baseline: 1.6247x; 1.6247x over previous
#include <cuda_runtime.h>
#include <cuda_bf16.h>
#include <stdint.h>

// RBF logits: out[b,c] = 2*dot(x[b],w[c]) - ||x[b]||^2 - ||w[c]||^2
// B=32768, C=4096, D=64. CTA tile 128x128, bf16 mma.sync, fp32 accum.
// Epilogue staged through conflict-free smem then cp.async.bulk (smem->gmem),
// eliminating the scattered-STG L1 wavefront storm measured in R1.

#define BM 128
#define BN 128
#define KD 64
#define PAD 72      // bf16 elems per tile row (144B): conflict-free frag LDS
#define SS  136     // floats per stage row (544B): mod32==8 -> conflict-free STS.v2

// dynamic smem layout (bytes):
//   [0, 69632)      stage (128 rows x 544B)  -- overlaps Xs/Ws (reused after MMA)
//   [0, 18432)        Xs tile (128 x 72 bf16)
//   [18432, 36864)    Ws tile
//   [69632, 70144)  xsq (128 f32)
//   [70144, 70656)  wsq (128 f32)
#define OFF_XS   0u
#define OFF_WS   18432u
#define OFF_XSQ  69632u
#define OFF_WSQ  70144u
#define SMEM_BYTES 70656u

static __device__ __forceinline__ uint32_t pack_bf16(float a, float b) {
    __nv_bfloat162 h = __floats2bfloat162_rn(a, b);
    return *reinterpret_cast<uint32_t*>(&h);
}
static __device__ __forceinline__ void sts64u(uint32_t addr, uint32_t a, uint32_t b) {
    asm volatile("st.shared.v2.b32 [%0], {%1,%2};" :: "r"(addr), "r"(a), "r"(b));
}
static __device__ __forceinline__ void sts64f(uint32_t addr, float a, float b) {
    asm volatile("st.shared.v2.f32 [%0], {%1,%2};" :: "r"(addr), "f"(a), "f"(b));
}

__global__ __launch_bounds__(256)
void rbf_logits_kernel(const float* __restrict__ x,
                       const float* __restrict__ w,
                       float* __restrict__ out,
                       int C) {
    extern __shared__ __align__(16) char smem[];
    const uint32_t sb = (uint32_t)__cvta_generic_to_shared(smem);
    __nv_bfloat16* Xs = reinterpret_cast<__nv_bfloat16*>(smem + OFF_XS);
    __nv_bfloat16* Ws = reinterpret_cast<__nv_bfloat16*>(smem + OFF_WS);
    float* xsq_s = reinterpret_cast<float*>(smem + OFF_XSQ);
    float* wsq_s = reinterpret_cast<float*>(smem + OFF_WSQ);

    const int tid  = threadIdx.x;
    const int lane = tid & 31;
    const int wid  = tid >> 5;
    const int row0 = blockIdx.y * BM;
    const int col0 = blockIdx.x * BN;

    // ---- Load X tile -> bf16 smem, with fused sum-of-squares reduce ----
    {
        const float4* g = reinterpret_cast<const float4*>(x + (size_t)row0 * KD);
        #pragma unroll
        for (int i = 0; i < 8; i++) {
            int idx = tid + i * 256;       // float4 index; 16 per row
            int r = idx >> 4, c4 = idx & 15;
            float4 v = g[idx];
            float ss = v.x*v.x + v.y*v.y + v.z*v.z + v.w*v.w;
            sts64u(sb + OFF_XS + (uint32_t)(r * PAD + c4 * 4) * 2u,
                   pack_bf16(v.x, v.y), pack_bf16(v.z, v.w));
            #pragma unroll
            for (int d = 8; d >= 1; d >>= 1) ss += __shfl_xor_sync(0xffffffffu, ss, d);
            if ((tid & 15) == 0) xsq_s[r] = ss;
        }
    }
    // ---- Load W tile -> bf16 smem, fused sum-of-squares ----
    {
        const float4* g = reinterpret_cast<const float4*>(w + (size_t)col0 * KD);
        #pragma unroll
        for (int i = 0; i < 8; i++) {
            int idx = tid + i * 256;
            int r = idx >> 4, c4 = idx & 15;
            float4 v = g[idx];
            float ss = v.x*v.x + v.y*v.y + v.z*v.z + v.w*v.w;
            sts64u(sb + OFF_WS + (uint32_t)(r * PAD + c4 * 4) * 2u,
                   pack_bf16(v.x, v.y), pack_bf16(v.z, v.w));
            #pragma unroll
            for (int d = 8; d >= 1; d >>= 1) ss += __shfl_xor_sync(0xffffffffu, ss, d);
            if ((tid & 15) == 0) wsq_s[r] = ss;
        }
    }
    __syncthreads();

    // ---- Warp tiling: 8 warps as 2(M) x 4(N); each warp 64x32 ----
    const int warp_m = wid >> 2;
    const int warp_n = wid & 3;
    const int m_base = warp_m * 64;
    const int n_base = warp_n * 32;
    const int lr = lane >> 2;   // 0..7
    const int lq = lane & 3;    // 0..3

    float acc[4][4][4];
    #pragma unroll
    for (int mi = 0; mi < 4; mi++)
        #pragma unroll
        for (int ni = 0; ni < 4; ni++)
            #pragma unroll
            for (int e = 0; e < 4; e++)
                acc[mi][ni][e] = 0.f;

    #pragma unroll
    for (int k0 = 0; k0 < KD; k0 += 16) {
        uint32_t afrag[4][4];
        #pragma unroll
        for (int mi = 0; mi < 4; mi++) {
            int r = m_base + mi * 16 + lr;
            const __nv_bfloat16* base = &Xs[r * PAD + k0 + lq * 2];
            afrag[mi][0] = *reinterpret_cast<const uint32_t*>(base);
            afrag[mi][1] = *reinterpret_cast<const uint32_t*>(base + 8 * PAD);
            afrag[mi][2] = *reinterpret_cast<const uint32_t*>(base + 8);
            afrag[mi][3] = *reinterpret_cast<const uint32_t*>(base + 8 * PAD + 8);
        }
        uint32_t bfrag[4][2];
        #pragma unroll
        for (int ni = 0; ni < 4; ni++) {
            int n = n_base + ni * 8 + lr;
            const __nv_bfloat16* base = &Ws[n * PAD + k0 + lq * 2];
            bfrag[ni][0] = *reinterpret_cast<const uint32_t*>(base);
            bfrag[ni][1] = *reinterpret_cast<const uint32_t*>(base + 8);
        }
        #pragma unroll
        for (int mi = 0; mi < 4; mi++) {
            #pragma unroll
            for (int ni = 0; ni < 4; ni++) {
                asm volatile(
                    "mma.sync.aligned.m16n8k16.row.col.f32.bf16.bf16.f32 "
                    "{%0,%1,%2,%3}, {%4,%5,%6,%7}, {%8,%9}, {%0,%1,%2,%3};\n"
                    : "+f"(acc[mi][ni][0]), "+f"(acc[mi][ni][1]),
                      "+f"(acc[mi][ni][2]), "+f"(acc[mi][ni][3])
                    : "r"(afrag[mi][0]), "r"(afrag[mi][1]),
                      "r"(afrag[mi][2]), "r"(afrag[mi][3]),
                      "r"(bfrag[ni][0]), "r"(bfrag[ni][1]));
            }
        }
    }

    // All frag LDS done before the stage region overwrites the tiles.
    __syncthreads();

    // ---- Epilogue: 2*acc - xsq - wsq staged into conflict-free smem ----
    #pragma unroll
    for (int mi = 0; mi < 4; mi++) {
        int rl0 = m_base + mi * 16 + lr;
        float xs0 = xsq_s[rl0];
        float xs1 = xsq_s[rl0 + 8];
        #pragma unroll
        for (int ni = 0; ni < 4; ni++) {
            int cl = n_base + ni * 8 + lq * 2;
            float ws0 = wsq_s[cl];
            float ws1 = wsq_s[cl + 1];
            uint32_t a0 = sb + (uint32_t)(rl0 * SS + cl) * 4u;
            uint32_t a1 = sb + (uint32_t)((rl0 + 8) * SS + cl) * 4u;
            sts64f(a0, 2.f * acc[mi][ni][0] - xs0 - ws0,
                       2.f * acc[mi][ni][1] - xs0 - ws1);
            sts64f(a1, 2.f * acc[mi][ni][2] - xs1 - ws0,
                       2.f * acc[mi][ni][3] - xs1 - ws1);
        }
    }
    asm volatile("fence.proxy.async.shared::cta;" ::: "memory");
    __syncthreads();

    // ---- Bulk copies smem -> gmem: warp w streams rows [w*16, w*16+16) ----
    if (lane == 0) {
        #pragma unroll
        for (int i = 0; i < 16; i++) {
            int r = wid * 16 + i;
            const float* dst = out + (size_t)(row0 + r) * C + col0;
            uint32_t src = sb + (uint32_t)r * (SS * 4u);
            asm volatile("cp.async.bulk.global.shared::cta.bulk_group [%0], [%1], %2;"
                         :: "l"(dst), "r"(src), "r"(512u) : "memory");
        }
        asm volatile("cp.async.bulk.commit_group;" ::: "memory");
        asm volatile("cp.async.bulk.wait_group 0;" ::: "memory");
    }
}

extern "C" void kernel_launch(void* const* d_in, const int* in_sizes, int n_in,
                              void* d_out, int out_size) {
    const float* x = (const float*)d_in[0];
    const float* w = (const float*)d_in[1];
    float* out = (float*)d_out;
    int B = in_sizes[0] / KD;   // 32768
    int C = in_sizes[1] / KD;   // 4096

    static int configured = 0;
    if (!configured) {
        cudaFuncSetAttribute(rbf_logits_kernel,
                             cudaFuncAttributeMaxDynamicSharedMemorySize, SMEM_BYTES);
        configured = 1;
    }
    dim3 grid(C / BN, B / BM);  // (32, 256)
    rbf_logits_kernel<<<grid, 256, SMEM_BYTES>>>(x, w, out, C);
}

// round 8
// speedup vs baseline: 1.6744x; 1.0306x over previous
#include <cuda_runtime.h>
#include <cuda_bf16.h>
#include <stdint.h>

// RBF logits: out[b,c] = 2*dot(x[b],w[c]) - ||x[b]||^2 - ||w[c]||^2
// B=32768, C=4096, D=64. CTA tile 128x128 processed as two 64-col halves
// (halves acc regs -> 3 CTAs/SM) with the half-0 TMA-store drain overlapping
// the half-1 MMA. Epilogue staged in conflict-free smem, cp.async.bulk out.
// (Resubmit of R4 kernel: previous round failed on container infra, not code.)

#define BM 128
#define BN 128
#define KD 64
#define PAD 72      // bf16 elems per tile row: conflict-free frag LDS
#define SS  72      // floats per stage row (288B): mod32==8 -> conflict-free STS.v2

// dynamic smem (bytes):
//   [0, 36864)       Xs (128x72 bf16) + Ws (128x72 bf16);  STAGE1 reuses this
//   [36864, 73728)   STAGE0 (128 rows x 288B)
//   [73728, 74752)   xsq / wsq (128 f32 each)
#define OFF_XS   0u
#define OFF_WS   18432u
#define STAGE1   0u
#define STAGE0   36864u
#define OFF_XSQ  73728u
#define OFF_WSQ  74240u
#define SMEM_BYTES 74752u

static __device__ __forceinline__ uint32_t pack_bf16(float a, float b) {
    __nv_bfloat162 h = __floats2bfloat162_rn(a, b);
    return *reinterpret_cast<uint32_t*>(&h);
}
static __device__ __forceinline__ void sts64u(uint32_t addr, uint32_t a, uint32_t b) {
    asm volatile("st.shared.v2.b32 [%0], {%1,%2};" :: "r"(addr), "r"(a), "r"(b));
}
static __device__ __forceinline__ void sts64f(uint32_t addr, float a, float b) {
    asm volatile("st.shared.v2.f32 [%0], {%1,%2};" :: "r"(addr), "f"(a), "f"(b));
}

__global__ __launch_bounds__(256, 3)
void rbf_logits_kernel(const float* __restrict__ x,
                       const float* __restrict__ w,
                       float* __restrict__ out,
                       int C) {
    extern __shared__ __align__(16) char smem[];
    const uint32_t sb = (uint32_t)__cvta_generic_to_shared(smem);
    __nv_bfloat16* Xs = reinterpret_cast<__nv_bfloat16*>(smem + OFF_XS);
    __nv_bfloat16* Ws = reinterpret_cast<__nv_bfloat16*>(smem + OFF_WS);
    float* xsq_s = reinterpret_cast<float*>(smem + OFF_XSQ);
    float* wsq_s = reinterpret_cast<float*>(smem + OFF_WSQ);

    const int tid  = threadIdx.x;
    const int lane = tid & 31;
    const int wid  = tid >> 5;
    const int row0 = blockIdx.y * BM;
    const int col0 = blockIdx.x * BN;

    // ---- Load X/W tiles -> bf16 smem with fused sum-of-squares reduce ----
    {
        const float4* g = reinterpret_cast<const float4*>(x + (size_t)row0 * KD);
        #pragma unroll
        for (int i = 0; i < 8; i++) {
            int idx = tid + i * 256;          // float4 index; 16 per row
            int r = idx >> 4, c4 = idx & 15;
            float4 v = g[idx];
            float ss = v.x*v.x + v.y*v.y + v.z*v.z + v.w*v.w;
            sts64u(sb + OFF_XS + (uint32_t)(r * PAD + c4 * 4) * 2u,
                   pack_bf16(v.x, v.y), pack_bf16(v.z, v.w));
            #pragma unroll
            for (int d = 8; d >= 1; d >>= 1) ss += __shfl_xor_sync(0xffffffffu, ss, d);
            if ((tid & 15) == 0) xsq_s[r] = ss;
        }
    }
    {
        const float4* g = reinterpret_cast<const float4*>(w + (size_t)col0 * KD);
        #pragma unroll
        for (int i = 0; i < 8; i++) {
            int idx = tid + i * 256;
            int r = idx >> 4, c4 = idx & 15;
            float4 v = g[idx];
            float ss = v.x*v.x + v.y*v.y + v.z*v.z + v.w*v.w;
            sts64u(sb + OFF_WS + (uint32_t)(r * PAD + c4 * 4) * 2u,
                   pack_bf16(v.x, v.y), pack_bf16(v.z, v.w));
            #pragma unroll
            for (int d = 8; d >= 1; d >>= 1) ss += __shfl_xor_sync(0xffffffffu, ss, d);
            if ((tid & 15) == 0) wsq_s[r] = ss;
        }
    }
    __syncthreads();

    // ---- Warp tiling per half: 8 warps as 2(M) x 4(N); warp = 64 x 16 ----
    const int warp_m = wid >> 2;
    const int warp_n = wid & 3;
    const int m_base = warp_m * 64;
    const int lr = lane >> 2;   // 0..7
    const int lq = lane & 3;    // 0..3

    #pragma unroll
    for (int h = 0; h < 2; h++) {
        const int n_base = h * 64 + warp_n * 16;    // global col within tile

        float acc[4][2][4];
        #pragma unroll
        for (int mi = 0; mi < 4; mi++)
            #pragma unroll
            for (int ni = 0; ni < 2; ni++)
                #pragma unroll
                for (int e = 0; e < 4; e++)
                    acc[mi][ni][e] = 0.f;

        #pragma unroll
        for (int k0 = 0; k0 < KD; k0 += 16) {
            uint32_t afrag[4][4];
            #pragma unroll
            for (int mi = 0; mi < 4; mi++) {
                int r = m_base + mi * 16 + lr;
                const __nv_bfloat16* base = &Xs[r * PAD + k0 + lq * 2];
                afrag[mi][0] = *reinterpret_cast<const uint32_t*>(base);
                afrag[mi][1] = *reinterpret_cast<const uint32_t*>(base + 8 * PAD);
                afrag[mi][2] = *reinterpret_cast<const uint32_t*>(base + 8);
                afrag[mi][3] = *reinterpret_cast<const uint32_t*>(base + 8 * PAD + 8);
            }
            uint32_t bfrag[2][2];
            #pragma unroll
            for (int ni = 0; ni < 2; ni++) {
                int n = n_base + ni * 8 + lr;
                const __nv_bfloat16* base = &Ws[n * PAD + k0 + lq * 2];
                bfrag[ni][0] = *reinterpret_cast<const uint32_t*>(base);
                bfrag[ni][1] = *reinterpret_cast<const uint32_t*>(base + 8);
            }
            #pragma unroll
            for (int mi = 0; mi < 4; mi++) {
                #pragma unroll
                for (int ni = 0; ni < 2; ni++) {
                    asm volatile(
                        "mma.sync.aligned.m16n8k16.row.col.f32.bf16.bf16.f32 "
                        "{%0,%1,%2,%3}, {%4,%5,%6,%7}, {%8,%9}, {%0,%1,%2,%3};\n"
                        : "+f"(acc[mi][ni][0]), "+f"(acc[mi][ni][1]),
                          "+f"(acc[mi][ni][2]), "+f"(acc[mi][ni][3])
                        : "r"(afrag[mi][0]), "r"(afrag[mi][1]),
                          "r"(afrag[mi][2]), "r"(afrag[mi][3]),
                          "r"(bfrag[ni][0]), "r"(bfrag[ni][1]));
                }
            }
        }

        const uint32_t stage = (h == 0) ? (sb + STAGE0) : (sb + STAGE1);
        // Half 1 stage overwrites the tiles: wait until all frag reads done.
        if (h == 1) __syncthreads();

        // ---- Epilogue: 2*acc - xsq - wsq into conflict-free stage ----
        #pragma unroll
        for (int mi = 0; mi < 4; mi++) {
            int rl0 = m_base + mi * 16 + lr;
            float xs0 = xsq_s[rl0];
            float xs1 = xsq_s[rl0 + 8];
            #pragma unroll
            for (int ni = 0; ni < 2; ni++) {
                int cg = n_base + ni * 8 + lq * 2;     // tile-global col
                int cl = cg - h * 64;                  // col within half
                float ws0 = wsq_s[cg];
                float ws1 = wsq_s[cg + 1];
                sts64f(stage + (uint32_t)(rl0 * SS + cl) * 4u,
                       2.f * acc[mi][ni][0] - xs0 - ws0,
                       2.f * acc[mi][ni][1] - xs0 - ws1);
                sts64f(stage + (uint32_t)((rl0 + 8) * SS + cl) * 4u,
                       2.f * acc[mi][ni][2] - xs1 - ws0,
                       2.f * acc[mi][ni][3] - xs1 - ws1);
            }
        }
        asm volatile("fence.proxy.async.shared::cta;" ::: "memory");
        __syncthreads();

        // ---- Bulk stores: warp w, lanes 0-15 -> rows w*16+lane, 256B each ----
        if (lane < 16) {
            int r = wid * 16 + lane;
            const float* dst = out + (size_t)(row0 + r) * C + col0 + h * 64;
            uint32_t src = stage + (uint32_t)r * (SS * 4u);
            asm volatile("cp.async.bulk.global.shared::cta.bulk_group [%0], [%1], %2;"
                         :: "l"(dst), "r"(src), "r"(256u) : "memory");
            asm volatile("cp.async.bulk.commit_group;" ::: "memory");
        }
        // No wait here for h==0: the drain overlaps the half-1 MMA.
    }

    // Drain all outstanding bulk stores before CTA exit.
    if (lane < 16)
        asm volatile("cp.async.bulk.wait_group 0;" ::: "memory");
}

extern "C" void kernel_launch(void* const* d_in, const int* in_sizes, int n_in,
                              void* d_out, int out_size) {
    const float* x = (const float*)d_in[0];
    const float* w = (const float*)d_in[1];
    float* out = (float*)d_out;
    int B = in_sizes[0] / KD;   // 32768
    int C = in_sizes[1] / KD;   // 4096

    cudaFuncSetAttribute(rbf_logits_kernel,
                         cudaFuncAttributeMaxDynamicSharedMemorySize, SMEM_BYTES);
    dim3 grid(C / BN, B / BM);  // (32, 256)
    rbf_logits_kernel<<<grid, 256, SMEM_BYTES>>>(x, w, out, C);
}